// round 16
// baseline (speedup 1.0000x reference)
#include <cuda_runtime.h>
#include <cstdint>

#define NH 32     // hidden
#define RK 6      // rank
#define BB 256    // batch
#define TT 2048   // time
#define DI 64     // input dim
#define DO 32     // output dim

#define RING  256     // guard window RING-64=192 >> B's lag (load-bearing!)
#define RINGM 255

// 64 MB scratch for x-projection (device global: allocation-free)
__device__ float g_xp[(size_t)BB * TT * NH];

// Packed fp32x2 ops (Blackwell)
__device__ __forceinline__ float2 fma2(const float2 a, const float2 b, const float2 c) {
    float2 d;
    asm("fma.rn.f32x2 %0, %1, %2, %3;"
        : "=l"(*(unsigned long long*)&d)
        : "l"(*(const unsigned long long*)&a),
          "l"(*(const unsigned long long*)&b),
          "l"(*(const unsigned long long*)&c));
    return d;
}
__device__ __forceinline__ float2 add2(const float2 a, const float2 b) {
    float2 d;
    asm("add.rn.f32x2 %0, %1, %2;"
        : "=l"(*(unsigned long long*)&d)
        : "l"(*(const unsigned long long*)&a),
          "l"(*(const unsigned long long*)&b));
    return d;
}

// ---------------------------------------------------------------------------
// Kernel 1 (verified register-tiled x-projection, ~83% of fp32 roofline):
// g_xp[b,t,n] = sum_i inputs[b,t,i]*W_in[n,i] + bias[n]
// ---------------------------------------------------------------------------
__global__ void __launch_bounds__(128) xproj_kernel(
    const float* __restrict__ inp, const float* __restrict__ Win,
    const float* __restrict__ bias)
{
    __shared__ __align__(16) float usm[64 * 68];        // 17.0 KB (pad 68)
    __shared__ __align__(16) float4 wsm4[16 * 32];      // 8 KB, swizzled

    const int tid = threadIdx.x;

    const float4* wg = (const float4*)Win;
    #pragma unroll
    for (int it = 0; it < 4; it++) {
        const int idx = tid + 128 * it;
        const int n = idx >> 4, c = idx & 15;
        wsm4[c * 32 + (n & 3) * 8 + (n >> 2)] = wg[idx];
    }

    const size_t base = (size_t)blockIdx.x * 64 * DI;
    const float4* ug = (const float4*)(inp + base);
    float4* us4 = (float4*)usm;
    #pragma unroll
    for (int it = 0; it < 8; it++) {
        const int idx = tid + 128 * it;
        const int row = idx >> 4, c4 = idx & 15;
        us4[row * 17 + c4] = ug[idx];
    }
    __syncthreads();

    const int w  = tid >> 5;
    const int l  = tid & 31;
    const int ng = l >> 2;
    const int rg = l & 3;
    const int rbase = w * 16;

    const float4* usr = us4 + (rbase + rg) * 17;

    float2 acc[4][4];
    #pragma unroll
    for (int ri = 0; ri < 4; ri++)
        #pragma unroll
        for (int nj = 0; nj < 4; nj++) acc[ri][nj] = make_float2(0.f, 0.f);

    #pragma unroll
    for (int c = 0; c < 16; c++) {
        float4 u4[4], w4[4];
        #pragma unroll
        for (int ri = 0; ri < 4; ri++) u4[ri] = usr[ri * 4 * 17 + c];
        #pragma unroll
        for (int nj = 0; nj < 4; nj++) w4[nj] = wsm4[c * 32 + nj * 8 + ng];
        #pragma unroll
        for (int ri = 0; ri < 4; ri++) {
            const float2 ulo = make_float2(u4[ri].x, u4[ri].y);
            const float2 uhi = make_float2(u4[ri].z, u4[ri].w);
            #pragma unroll
            for (int nj = 0; nj < 4; nj++) {
                acc[ri][nj] = fma2(ulo, make_float2(w4[nj].x, w4[nj].y), acc[ri][nj]);
                acc[ri][nj] = fma2(uhi, make_float2(w4[nj].z, w4[nj].w), acc[ri][nj]);
            }
        }
    }

    const float4 b4 = *(const float4*)(bias + ng * 4);
    const size_t row0 = (size_t)blockIdx.x * 64 + rbase + rg;
    #pragma unroll
    for (int ri = 0; ri < 4; ri++) {
        float4 o;
        o.x = acc[ri][0].x + acc[ri][0].y + b4.x;
        o.y = acc[ri][1].x + acc[ri][1].y + b4.y;
        o.z = acc[ri][2].x + acc[ri][2].y + b4.z;
        o.w = acc[ri][3].x + acc[ri][3].y + b4.w;
        *(float4*)&g_xp[(row0 + ri * 4) * NH + ng * 4] = o;
    }
}

// ---------------------------------------------------------------------------
// Kernel 2: warp-specialized recurrence (R15 structure, MUFU.TANH).
// ONE change: base-folded chain. Cross-iteration chain is now a single FADD:
//   pre_t = sp_{t-1} + d_t,   d_t = 0.9*p_{t-2}... precisely:
//   carry pb = 0.9*p_{t-2}, d = pb + x_t (computed off-chain in iter t-1);
//   iter t: pre = sp + d; v = tanh(pre); broadcast; matvec -> sp_new;
//           off-chain: pprev = pb + sp; pb = 0.9*pprev; d = pb + x_{t+1}.
//   Warp A (wid 0): p-recurrence; v -> ring. Warp B (wid 1): q/h/y.
// ---------------------------------------------------------------------------
__global__ void __launch_bounds__(64) rnn_kernel(
    const float* __restrict__ m, const float* __restrict__ nv,
    const float* __restrict__ Mm, const float* __restrict__ Nm,
    const float* __restrict__ Wout, const float* __restrict__ bout,
    float* __restrict__ out, float* __restrict__ hfin)
{
    __shared__ __align__(16) float ring[RING][NH];   // 32 KB
    __shared__ unsigned progress;
    __shared__ unsigned bdone;

    const int b   = blockIdx.x;
    const int wid = threadIdx.x >> 5;
    const int l   = threadIdx.x & 31;

    if (threadIdx.x == 0) { progress = 0u; bdone = 0u; }
    __syncthreads();

    if (wid == 0) {
        // ================= WARP A: critical chain =================
        float Ml[RK];
        const float ml = m[l];
        #pragma unroll
        for (int j = 0; j < RK; j++) Ml[j] = Mm[l * RK + j];

        float2 wr2[NH / 2];
        #pragma unroll
        for (int k = 0; k < NH; k += 2) {
            float s0 = ml * nv[k], s1 = ml * nv[k + 1];
            #pragma unroll
            for (int j = 0; j < RK; j++) {
                s0 = fmaf(Ml[j], Nm[k * RK + j], s0);
                s1 = fmaf(Ml[j], Nm[(k + 1) * RK + j], s1);
            }
            wr2[k / 2] = make_float2(0.1f * s0, 0.1f * s1);
        }

        const float* xp = g_xp + (size_t)b * TT * NH + l;

        float xa[8], xn[8];
        #pragma unroll
        for (int i = 0; i < 8; i++) xa[i] = xp[(size_t)i * NH];

        // folded state: sp = last matvec; pb = 0.9*p_prev2; d = pb + x_t
        float sp = 0.f;
        float pb = 0.f;
        float d  = xa[0];

        for (int c = 0; c < TT / 8; c++) {
            const int t0 = c * 8;
            if (c + 1 < TT / 8) {
                #pragma unroll
                for (int i = 0; i < 8; i++) xn[i] = xp[(size_t)(t0 + 8 + i) * NH];
            }
            #pragma unroll
            for (int s = 0; s < 8; s++) {
                const int t = t0 + s;

                const float pre = sp + d;           // single chain FADD
                float v;
                asm("tanh.approx.f32 %0, %1;" : "=f"(v) : "f"(pre));

                // off-chain state fold (runs in MUFU/broadcast shadow)
                const float pprev = pb + sp;        // p_{t-1}
                pb = 0.9f * pprev;
                const float xnext = (s == 7) ? xn[0] : xa[s + 1];
                d = pb + xnext;

                ring[t & RINGM][l] = v;
                __syncwarp();

                const float4* r4p = (const float4*)ring[t & RINGM];
                float2 ap0 = make_float2(0.f, 0.f), ap1 = ap0, ap2 = ap0, ap3 = ap0;
                #pragma unroll
                for (int j = 0; j < NH / 4; j++) {
                    const float4 r4 = r4p[j];
                    const float2 lo = make_float2(r4.x, r4.y);
                    const float2 hi = make_float2(r4.z, r4.w);
                    float2 acc = (j & 3) == 0 ? ap0 : (j & 3) == 1 ? ap1 : (j & 3) == 2 ? ap2 : ap3;
                    acc = fma2(wr2[2 * j + 0], lo, acc);
                    acc = fma2(wr2[2 * j + 1], hi, acc);
                    if ((j & 3) == 0) ap0 = acc; else if ((j & 3) == 1) ap1 = acc;
                    else if ((j & 3) == 2) ap2 = acc; else ap3 = acc;
                }
                const float2 sp2 = add2(add2(ap0, ap1), add2(ap2, ap3));
                sp = sp2.x + sp2.y;
            }
            #pragma unroll
            for (int i = 0; i < 8; i++) xa[i] = xn[i];

            if ((c & 3) == 3) {
                __threadfence_block();
                __syncwarp();
                if (l == 0)
                    *(volatile unsigned*)&progress = (unsigned)(t0 + 8);
                if (l == 0) {
                    while ((int)(t0 + 8) - (int)(*(volatile unsigned*)&bdone) > RING - 64)
                        __nanosleep(100);
                }
                __syncwarp();
            }
        }
    } else {
        // ================= WARP B: trailing q/h/y =================
        float2 wo2[NH / 2];
        #pragma unroll
        for (int k = 0; k < NH; k += 2)
            wo2[k / 2] = make_float2(0.1f * Wout[l * NH + k], 0.1f * Wout[l * NH + k + 1]);
        const float bo = bout[l];

        float* yo = out + (size_t)b * TT * DO + l;
        float q = 0.f, h = 0.f;

        for (int blk = 0; blk < TT / 32; blk++) {
            const int tend = (blk + 1) * 32;
            if (l == 0) {
                while ((int)(*(volatile unsigned*)&progress) < tend)
                    __nanosleep(150);
            }
            __syncwarp();
            __threadfence_block();   // acquire: ring writes visible

            for (int t = blk * 32; t < tend; t++) {
                const float4* r4p = (const float4*)ring[t & RINGM];
                float2 aq0 = make_float2(0.f, 0.f), aq1 = aq0, aq2 = aq0, aq3 = aq0;
                #pragma unroll
                for (int j = 0; j < NH / 4; j++) {
                    const float4 r4 = r4p[j];
                    const float2 lo = make_float2(r4.x, r4.y);
                    const float2 hi = make_float2(r4.z, r4.w);
                    float2 acc = (j & 3) == 0 ? aq0 : (j & 3) == 1 ? aq1 : (j & 3) == 2 ? aq2 : aq3;
                    acc = fma2(wo2[2 * j + 0], lo, acc);
                    acc = fma2(wo2[2 * j + 1], hi, acc);
                    if ((j & 3) == 0) aq0 = acc; else if ((j & 3) == 1) aq1 = acc;
                    else if ((j & 3) == 2) aq2 = acc; else aq3 = acc;
                }
                const float2 sq2 = add2(add2(aq0, aq1), add2(aq2, aq3));
                const float vl = ring[t & RINGM][l];

                q = 0.9f * q + (sq2.x + sq2.y);
                h = fmaf(0.9f, h, 0.1f * vl);

                yo[(size_t)t * DO] = q + bo;
            }

            if (l == 0) {
                __threadfence_block();
                *(volatile unsigned*)&bdone = (unsigned)tend;
            }
        }

        if (hfin) hfin[b * NH + l] = h;
    }
}

// ---------------------------------------------------------------------------
extern "C" void kernel_launch(void* const* d_in, const int* in_sizes, int n_in,
                              void* d_out, int out_size) {
    const float* inputs = (const float*)d_in[0];
    const float* W_in   = (const float*)d_in[1];
    const float* m_     = (const float*)d_in[2];
    const float* n_     = (const float*)d_in[3];
    const float* M_     = (const float*)d_in[4];
    const float* Nm_    = (const float*)d_in[5];
    const float* bias   = (const float*)d_in[6];
    const float* Wout   = (const float*)d_in[7];
    const float* bout   = (const float*)d_in[8];

    float* out = (float*)d_out;
    float* hf = nullptr;
    const long long need = (long long)BB * TT * NH + (long long)BB * NH;
    if ((long long)out_size >= need)
        hf = out + (size_t)BB * TT * NH;

    xproj_kernel<<<BB * TT / 64, 128>>>(inputs, W_in, bias);
    rnn_kernel<<<BB, 64>>>(m_, n_, M_, Nm_, Wout, bout, out, hf);
}

// round 17
// speedup vs baseline: 1.0925x; 1.0925x over previous
#include <cuda_runtime.h>
#include <cstdint>

#define NH 32     // hidden
#define RK 6      // rank
#define BB 256    // batch
#define TT 2048   // time
#define DI 64     // input dim
#define DO 32     // output dim

#define RING  256     // guard window RING-64=192 >> B's lag (load-bearing!)
#define RINGM 255

// 64 MB scratch for x-projection (device global: allocation-free)
__device__ float g_xp[(size_t)BB * TT * NH];

// Packed fp32x2 ops (Blackwell)
__device__ __forceinline__ float2 fma2(const float2 a, const float2 b, const float2 c) {
    float2 d;
    asm("fma.rn.f32x2 %0, %1, %2, %3;"
        : "=l"(*(unsigned long long*)&d)
        : "l"(*(const unsigned long long*)&a),
          "l"(*(const unsigned long long*)&b),
          "l"(*(const unsigned long long*)&c));
    return d;
}
__device__ __forceinline__ float2 add2(const float2 a, const float2 b) {
    float2 d;
    asm("add.rn.f32x2 %0, %1, %2;"
        : "=l"(*(unsigned long long*)&d)
        : "l"(*(const unsigned long long*)&a),
          "l"(*(const unsigned long long*)&b));
    return d;
}

// ---------------------------------------------------------------------------
// Kernel 1 (v3): register-tiled x-projection, 8 rows x 4 outputs per lane.
// g_xp[b,t,n] = sum_i inputs[b,t,i]*W_in[n,i] + bias[n]
// 128 threads, 128 rows/block. Per c-iter: 12 LDS.128 feed 64 fma2.
// u smem stride 17 float4 (rg-lanes -> bank quads 0/4/8/12, 8-way bcast);
// W swizzled (n&3)*8+(n>>2) -> per-nj LDS conflict-free across ng.
// ---------------------------------------------------------------------------
__global__ void __launch_bounds__(128) xproj_kernel(
    const float* __restrict__ inp, const float* __restrict__ Win,
    const float* __restrict__ bias)
{
    __shared__ __align__(16) float4 us4[128 * 17];      // 34.8 KB
    __shared__ __align__(16) float4 wsm4[16 * 32];      // 8 KB, swizzled

    const int tid = threadIdx.x;

    // Stage W: 512 float4; n = idx>>4, c = idx&15
    const float4* wg = (const float4*)Win;
    #pragma unroll
    for (int it = 0; it < 4; it++) {
        const int idx = tid + 128 * it;
        const int n = idx >> 4, c = idx & 15;
        wsm4[c * 32 + (n & 3) * 8 + (n >> 2)] = wg[idx];
    }

    // Stage u: 128 rows x 16 float4, padded row stride 17 float4
    const size_t base = (size_t)blockIdx.x * 128 * DI;
    const float4* ug = (const float4*)(inp + base);
    #pragma unroll
    for (int it = 0; it < 16; it++) {
        const int idx = tid + 128 * it;
        const int row = idx >> 4, c4 = idx & 15;
        us4[row * 17 + c4] = ug[idx];
    }
    __syncthreads();

    const int w  = tid >> 5;
    const int l  = tid & 31;
    const int ng = l >> 2;
    const int rg = l & 3;
    const int rbase = w * 32;

    const float4* usr = us4 + (rbase + rg) * 17;    // +ri*4*17 per ri

    float2 acc[8][4];
    #pragma unroll
    for (int ri = 0; ri < 8; ri++)
        #pragma unroll
        for (int nj = 0; nj < 4; nj++) acc[ri][nj] = make_float2(0.f, 0.f);

    #pragma unroll
    for (int c = 0; c < 16; c++) {
        float4 w4[4];
        #pragma unroll
        for (int nj = 0; nj < 4; nj++) w4[nj] = wsm4[c * 32 + nj * 8 + ng];
        #pragma unroll
        for (int ri = 0; ri < 8; ri++) {
            const float4 u4 = usr[ri * 4 * 17 + c];
            const float2 ulo = make_float2(u4.x, u4.y);
            const float2 uhi = make_float2(u4.z, u4.w);
            #pragma unroll
            for (int nj = 0; nj < 4; nj++) {
                acc[ri][nj] = fma2(ulo, make_float2(w4[nj].x, w4[nj].y), acc[ri][nj]);
                acc[ri][nj] = fma2(uhi, make_float2(w4[nj].z, w4[nj].w), acc[ri][nj]);
            }
        }
    }

    const float4 b4 = *(const float4*)(bias + ng * 4);
    const size_t row0 = (size_t)blockIdx.x * 128 + rbase + rg;
    #pragma unroll
    for (int ri = 0; ri < 8; ri++) {
        float4 o;
        o.x = acc[ri][0].x + acc[ri][0].y + b4.x;
        o.y = acc[ri][1].x + acc[ri][1].y + b4.y;
        o.z = acc[ri][2].x + acc[ri][2].y + b4.z;
        o.w = acc[ri][3].x + acc[ri][3].y + b4.w;
        *(float4*)&g_xp[(row0 + ri * 4) * NH + ng * 4] = o;
    }
}

// ---------------------------------------------------------------------------
// Kernel 2: warp-specialized recurrence — EXACT R15 (proven 171us).
//   Warp A (wid 0): p <- 0.9p + (0.1*W_rec)·v; v = tanh.approx(pre) -> ring.
//   Warp B (wid 1): q <- 0.9q + (0.1*W_out)·v; y = q + b_out; h-final.
// ---------------------------------------------------------------------------
__global__ void __launch_bounds__(64) rnn_kernel(
    const float* __restrict__ m, const float* __restrict__ nv,
    const float* __restrict__ Mm, const float* __restrict__ Nm,
    const float* __restrict__ Wout, const float* __restrict__ bout,
    float* __restrict__ out, float* __restrict__ hfin)
{
    __shared__ __align__(16) float ring[RING][NH];   // 32 KB
    __shared__ unsigned progress;
    __shared__ unsigned bdone;

    const int b   = blockIdx.x;
    const int wid = threadIdx.x >> 5;
    const int l   = threadIdx.x & 31;

    if (threadIdx.x == 0) { progress = 0u; bdone = 0u; }
    __syncthreads();

    if (wid == 0) {
        // ================= WARP A: critical chain =================
        float Ml[RK];
        const float ml = m[l];
        #pragma unroll
        for (int j = 0; j < RK; j++) Ml[j] = Mm[l * RK + j];

        float2 wr2[NH / 2];
        #pragma unroll
        for (int k = 0; k < NH; k += 2) {
            float s0 = ml * nv[k], s1 = ml * nv[k + 1];
            #pragma unroll
            for (int j = 0; j < RK; j++) {
                s0 = fmaf(Ml[j], Nm[k * RK + j], s0);
                s1 = fmaf(Ml[j], Nm[(k + 1) * RK + j], s1);
            }
            wr2[k / 2] = make_float2(0.1f * s0, 0.1f * s1);
        }

        const float* xp = g_xp + (size_t)b * TT * NH + l;
        float p = 0.f;

        float xa[8], xn[8];
        #pragma unroll
        for (int i = 0; i < 8; i++) xa[i] = xp[(size_t)i * NH];

        for (int c = 0; c < TT / 8; c++) {
            const int t0 = c * 8;
            if (c + 1 < TT / 8) {
                #pragma unroll
                for (int i = 0; i < 8; i++) xn[i] = xp[(size_t)(t0 + 8 + i) * NH];
            }
            #pragma unroll
            for (int s = 0; s < 8; s++) {
                const int t = t0 + s;
                const float pre = p + xa[s];
                float v;
                asm("tanh.approx.f32 %0, %1;" : "=f"(v) : "f"(pre));

                const float pbase = 0.9f * p;     // in MUFU shadow

                ring[t & RINGM][l] = v;
                __syncwarp();

                const float4* r4p = (const float4*)ring[t & RINGM];
                float2 ap0 = make_float2(0.f, 0.f), ap1 = ap0, ap2 = ap0, ap3 = ap0;
                #pragma unroll
                for (int j = 0; j < NH / 4; j++) {
                    const float4 r4 = r4p[j];
                    const float2 lo = make_float2(r4.x, r4.y);
                    const float2 hi = make_float2(r4.z, r4.w);
                    float2 acc = (j & 3) == 0 ? ap0 : (j & 3) == 1 ? ap1 : (j & 3) == 2 ? ap2 : ap3;
                    acc = fma2(wr2[2 * j + 0], lo, acc);
                    acc = fma2(wr2[2 * j + 1], hi, acc);
                    if ((j & 3) == 0) ap0 = acc; else if ((j & 3) == 1) ap1 = acc;
                    else if ((j & 3) == 2) ap2 = acc; else ap3 = acc;
                }
                const float2 sp2 = add2(add2(ap0, ap1), add2(ap2, ap3));
                p = pbase + (sp2.x + sp2.y);
            }
            #pragma unroll
            for (int i = 0; i < 8; i++) xa[i] = xn[i];

            if ((c & 3) == 3) {
                __threadfence_block();
                __syncwarp();
                if (l == 0)
                    *(volatile unsigned*)&progress = (unsigned)(t0 + 8);
                if (l == 0) {
                    while ((int)(t0 + 8) - (int)(*(volatile unsigned*)&bdone) > RING - 64)
                        __nanosleep(100);
                }
                __syncwarp();
            }
        }
    } else {
        // ================= WARP B: trailing q/h/y =================
        float2 wo2[NH / 2];
        #pragma unroll
        for (int k = 0; k < NH; k += 2)
            wo2[k / 2] = make_float2(0.1f * Wout[l * NH + k], 0.1f * Wout[l * NH + k + 1]);
        const float bo = bout[l];

        float* yo = out + (size_t)b * TT * DO + l;
        float q = 0.f, h = 0.f;

        for (int blk = 0; blk < TT / 32; blk++) {
            const int tend = (blk + 1) * 32;
            if (l == 0) {
                while ((int)(*(volatile unsigned*)&progress) < tend)
                    __nanosleep(150);
            }
            __syncwarp();
            __threadfence_block();   // acquire: ring writes visible

            for (int t = blk * 32; t < tend; t++) {
                const float4* r4p = (const float4*)ring[t & RINGM];
                float2 aq0 = make_float2(0.f, 0.f), aq1 = aq0, aq2 = aq0, aq3 = aq0;
                #pragma unroll
                for (int j = 0; j < NH / 4; j++) {
                    const float4 r4 = r4p[j];
                    const float2 lo = make_float2(r4.x, r4.y);
                    const float2 hi = make_float2(r4.z, r4.w);
                    float2 acc = (j & 3) == 0 ? aq0 : (j & 3) == 1 ? aq1 : (j & 3) == 2 ? aq2 : aq3;
                    acc = fma2(wo2[2 * j + 0], lo, acc);
                    acc = fma2(wo2[2 * j + 1], hi, acc);
                    if ((j & 3) == 0) aq0 = acc; else if ((j & 3) == 1) aq1 = acc;
                    else if ((j & 3) == 2) aq2 = acc; else aq3 = acc;
                }
                const float2 sq2 = add2(add2(aq0, aq1), add2(aq2, aq3));
                const float vl = ring[t & RINGM][l];

                q = 0.9f * q + (sq2.x + sq2.y);
                h = fmaf(0.9f, h, 0.1f * vl);

                yo[(size_t)t * DO] = q + bo;
            }

            if (l == 0) {
                __threadfence_block();
                *(volatile unsigned*)&bdone = (unsigned)tend;
            }
        }

        if (hfin) hfin[b * NH + l] = h;
    }
}

// ---------------------------------------------------------------------------
extern "C" void kernel_launch(void* const* d_in, const int* in_sizes, int n_in,
                              void* d_out, int out_size) {
    const float* inputs = (const float*)d_in[0];
    const float* W_in   = (const float*)d_in[1];
    const float* m_     = (const float*)d_in[2];
    const float* n_     = (const float*)d_in[3];
    const float* M_     = (const float*)d_in[4];
    const float* Nm_    = (const float*)d_in[5];
    const float* bias   = (const float*)d_in[6];
    const float* Wout   = (const float*)d_in[7];
    const float* bout   = (const float*)d_in[8];

    float* out = (float*)d_out;
    float* hf = nullptr;
    const long long need = (long long)BB * TT * NH + (long long)BB * NH;
    if ((long long)out_size >= need)
        hf = out + (size_t)BB * TT * NH;

    xproj_kernel<<<BB * TT / 128, 128>>>(inputs, W_in, bias);
    rnn_kernel<<<BB, 64>>>(m_, n_, M_, Nm_, Wout, bout, out, hf);
}